// round 7
// baseline (speedup 1.0000x reference)
#include <cuda_runtime.h>
#include <math.h>

// ---------------- problem constants ----------------
#define NB   4      // branches
#define NL   3      // layers
#define BSZ  4      // batch
#define TSZ  1024   // sequence
#define DIN  32
#define DM   128    // d_model
#define DI   256    // d_inner
#define DS   16     // d_state
#define DC   4      // d_conv
#define DTR  8      // dt_rank
#define EMB  64
#define NTOK (BSZ*TSZ)      // 4096 tokens per branch
#define NCH  8              // scan chunks
#define CLEN (TSZ/NCH)      // 128 steps per chunk
#define EPSV 1e-7f
#define MAXN 10.0f

// ---------------- device scratch (no allocations allowed) ----------------
__device__ float g_h  [NB*NTOK*DM];        // 8 MB   hidden (d_model)
__device__ float g_xz [NB*NTOK*2*DI];      // 32 MB  in_proj output (xp | z)
__device__ float g_xc [NB*NTOK*DI];        // 16 MB  conv+silu output
__device__ float g_dbl[NB*NTOK*40];        // 2.6 MB dt_rank + B + C
__device__ float g_dt [NB*NTOK*DI];        // 16 MB  softplus(dt)
__device__ float g_y  [NB*NTOK*DI];        // 16 MB  scan output * silu(z)
__device__ float g_q  [NB*BSZ*NCH*DI*DS];  // 8 MB   per-chunk end state (from 0)
__device__ float g_S  [NB*BSZ*NCH*DI];     // 0.5 MB per-chunk sum(dt)
__device__ float g_mean[NB*BSZ*DM];
__device__ float g_zt [NB*BSZ*EMB];

__device__ __forceinline__ float siluf(float x) { return x / (1.f + __expf(-x)); }

// ---------------- input projection: h = x @ W_ip + b_ip ----------------
__global__ void k_inproj(const float* __restrict__ x0, const float* __restrict__ x1,
                         const float* __restrict__ x2, const float* __restrict__ x3,
                         const float* __restrict__ Wip, const float* __restrict__ bip)
{
    int idx = blockIdx.x * 256 + threadIdx.x;          // NB*NTOK*DM = 2^21
    int dm  = idx & (DM - 1);
    int n   = (idx >> 7) & (NTOK - 1);
    int br  = idx >> 19;
    const float* X = (br == 0) ? x0 : (br == 1) ? x1 : (br == 2) ? x2 : x3;
    const float* xr = X + n * DIN;
    const float* w  = Wip + br * DIN * DM + dm;
    float acc = bip[br * DM + dm];
#pragma unroll
    for (int k = 0; k < DIN; k++) acc += xr[k] * w[k * DM];
    g_h[idx] = acc;
}

// ---------------- generic batched SGEMM: C = A @ B (per branch) ----------------
// BM=128, BN=64, BK=16, 256 threads, 8x4 per thread.
__global__ __launch_bounds__(256) void k_sgemm(
    const float* __restrict__ A, const float* __restrict__ B, float* __restrict__ C,
    int M, int N, int K, int sA, int sB, int sC)
{
    const int BM = 128, BN = 64, BK = 16, TM = 8, TN = 4;
    A += (size_t)blockIdx.z * sA;
    B += (size_t)blockIdx.z * sB;
    C += (size_t)blockIdx.z * sC;
    int bm = blockIdx.y * BM, bn = blockIdx.x * BN;

    __shared__ float As[BM][BK];
    __shared__ __align__(16) float Bs[BK][BN];

    int tid  = threadIdx.x;
    int trow = (tid >> 4) * TM;
    int tcol = (tid & 15) * TN;

    float acc[TM][TN];
#pragma unroll
    for (int i = 0; i < TM; i++)
#pragma unroll
        for (int j = 0; j < TN; j++) acc[i][j] = 0.f;

    for (int k0 = 0; k0 < K; k0 += BK) {
#pragma unroll
        for (int i = 0; i < (BM * BK) / 256; i++) {      // 8 loads
            int e  = tid + i * 256;
            int m  = e >> 4, kk = e & 15;
            As[m][kk] = A[(size_t)(bm + m) * K + k0 + kk];
        }
#pragma unroll
        for (int i = 0; i < (BK * BN) / 256; i++) {      // 4 loads
            int e  = tid + i * 256;
            int kk = e >> 6, nn = e & 63;
            float v = 0.f;
            if (bn + nn < N) v = B[(size_t)(k0 + kk) * N + bn + nn];
            Bs[kk][nn] = v;
        }
        __syncthreads();
#pragma unroll
        for (int kk = 0; kk < BK; kk++) {
            float a[TM];
#pragma unroll
            for (int i = 0; i < TM; i++) a[i] = As[trow + i][kk];
            float4 bv = *reinterpret_cast<const float4*>(&Bs[kk][tcol]);
            float bb[TN] = { bv.x, bv.y, bv.z, bv.w };
#pragma unroll
            for (int i = 0; i < TM; i++)
#pragma unroll
                for (int j = 0; j < TN; j++) acc[i][j] += a[i] * bb[j];
        }
        __syncthreads();
    }
#pragma unroll
    for (int i = 0; i < TM; i++) {
        int m = bm + trow + i;
#pragma unroll
        for (int j = 0; j < TN; j++) {
            int n = bn + tcol + j;
            if (n < N) C[(size_t)m * N + n] = acc[i][j];
        }
    }
}

// ---------------- causal depthwise conv (k=4) + silu ----------------
__global__ void k_convsilu(const float* __restrict__ cw, const float* __restrict__ cb, int l)
{
    int idx = blockIdx.x * 256 + threadIdx.x;          // NB*NTOK*DI = 2^22
    int d   = idx & (DI - 1);
    int n   = (idx >> 8) & (NTOK - 1);
    int br  = idx >> 20;
    int t = n & (TSZ - 1), b = n >> 10;
    const float* w = cw + ((br * NL + l) * DI + d) * DC;
    float acc = cb[(br * NL + l) * DI + d];
    int base = (br * NTOK + b * TSZ) * (2 * DI);
#pragma unroll
    for (int k = 0; k < DC; k++) {
        int tt = t + k - (DC - 1);
        if (tt >= 0) acc += g_xz[base + tt * (2 * DI) + d] * w[k];
    }
    g_xc[idx] = siluf(acc);
}

// ---------------- dt = softplus(dbl[:,:8] @ W_dt + b_dt) ----------------
__global__ void k_dt(const float* __restrict__ Wdt, const float* __restrict__ bdt, int l)
{
    int idx = blockIdx.x * 256 + threadIdx.x;
    int d   = idx & (DI - 1);
    int n   = (idx >> 8) & (NTOK - 1);
    int br  = idx >> 20;
    const float* db = &g_dbl[(br * NTOK + n) * 40];
    const float* w  = Wdt + (br * NL + l) * DTR * DI + d;
    float acc = bdt[(br * NL + l) * DI + d];
#pragma unroll
    for (int r = 0; r < DTR; r++) acc += db[r] * w[r * DI];
    g_dt[idx] = (acc > 20.f) ? acc : log1pf(__expf(acc));
}

// ---------------- scan pass 1: per-chunk (q, S) from zero initial state ----------------
__global__ __launch_bounds__(256) void k_scan1(const float* __restrict__ Alog, int l)
{
    int c = blockIdx.x, b = blockIdx.y, br = blockIdx.z;
    int d = threadIdx.x;
    const float* ap = Alog + ((size_t)(br * NL + l) * DI + d) * DS;
    float As[DS], h[DS];
#pragma unroll
    for (int s = 0; s < DS; s++) { As[s] = -__expf(ap[s]); h[s] = 0.f; }
    float Ssum = 0.f;
    __shared__ float sB[32][DS];
    int nbase = br * NTOK + b * TSZ + c * CLEN;
    for (int tb = 0; tb < CLEN; tb += 32) {
        __syncthreads();
#pragma unroll
        for (int i = 0; i < 2; i++) {
            int e = threadIdx.x + i * 256;
            int row = e >> 4, s = e & 15;
            sB[row][s] = g_dbl[(size_t)(nbase + tb + row) * 40 + 8 + s];
        }
        __syncthreads();
#pragma unroll 4
        for (int i = 0; i < 32; i++) {
            int tok = nbase + tb + i;
            float dt = g_dt[(size_t)tok * DI + d];
            float xc = g_xc[(size_t)tok * DI + d];
            float u  = dt * xc;
            Ssum += dt;
#pragma unroll
            for (int s = 0; s < DS; s++)
                h[s] = __expf(dt * As[s]) * h[s] + u * sB[i][s];
        }
    }
    int qo = (((br * BSZ + b) * NCH + c) * DI + d) * DS;
#pragma unroll
    for (int s = 0; s < DS; s++) g_q[qo + s] = h[s];
    g_S[((br * BSZ + b) * NCH + c) * DI + d] = Ssum;
}

// ---------------- scan pass 2: fold prefix chunks, emit y*silu(z)+D*xc ----------------
__global__ __launch_bounds__(256) void k_scan2(const float* __restrict__ Alog,
                                               const float* __restrict__ Dpar, int l)
{
    int c = blockIdx.x, b = blockIdx.y, br = blockIdx.z;
    int d = threadIdx.x;
    const float* ap = Alog + ((size_t)(br * NL + l) * DI + d) * DS;
    float As[DS], h[DS];
#pragma unroll
    for (int s = 0; s < DS; s++) { As[s] = -__expf(ap[s]); h[s] = 0.f; }

    // initial state for this chunk: fold chunks 0..c-1
    for (int j = 0; j < c; j++) {
        float Sj = g_S[((br * BSZ + b) * NCH + j) * DI + d];
        int qo = (((br * BSZ + b) * NCH + j) * DI + d) * DS;
#pragma unroll
        for (int s = 0; s < DS; s++)
            h[s] = __expf(As[s] * Sj) * h[s] + g_q[qo + s];
    }
    float Dp = Dpar[(br * NL + l) * DI + d];

    __shared__ float sB[32][DS];
    __shared__ float sC[32][DS];
    int nbase = br * NTOK + b * TSZ + c * CLEN;
    for (int tb = 0; tb < CLEN; tb += 32) {
        __syncthreads();
#pragma unroll
        for (int i = 0; i < 4; i++) {
            int e = threadIdx.x + i * 256;      // 32 rows x 32 (B|C)
            int row = e >> 5, s = e & 31;
            float v = g_dbl[(size_t)(nbase + tb + row) * 40 + 8 + s];
            if (s < 16) sB[row][s] = v; else sC[row][s - 16] = v;
        }
        __syncthreads();
#pragma unroll 2
        for (int i = 0; i < 32; i++) {
            int tok = nbase + tb + i;
            float dt = g_dt[(size_t)tok * DI + d];
            float xc = g_xc[(size_t)tok * DI + d];
            float u  = dt * xc;
            float y  = 0.f;
#pragma unroll
            for (int s = 0; s < DS; s++) {
                h[s] = __expf(dt * As[s]) * h[s] + u * sB[i][s];
                y += h[s] * sC[i][s];
            }
            float z = g_xz[(size_t)tok * (2 * DI) + DI + d];
            g_y[(size_t)tok * DI + d] = (y + Dp * xc) * siluf(z);
        }
    }
}

// ---------------- mean over T ----------------
__global__ void k_mean()
{
    int g = blockIdx.x;                 // NB*BSZ = 16
    int d = threadIdx.x;                // 128
    int br = g >> 2, b = g & 3;
    int base = (br * NTOK + b * TSZ) * DM + d;
    float a0 = 0.f, a1 = 0.f, a2 = 0.f, a3 = 0.f;
    for (int t = 0; t < TSZ; t += 4) {
        a0 += g_h[base + (t + 0) * DM];
        a1 += g_h[base + (t + 1) * DM];
        a2 += g_h[base + (t + 2) * DM];
        a3 += g_h[base + (t + 3) * DM];
    }
    g_mean[g * DM + d] = (a0 + a1 + a2 + a3) * (1.f / TSZ);
}

// ---------------- head: z_t = mean @ W_op + b_op (also writes d_out) ----------------
__global__ void k_head(const float* __restrict__ Wop, const float* __restrict__ bop,
                       float* __restrict__ out)
{
    int idx = blockIdx.x * 256 + threadIdx.x;   // 1024
    int e = idx & 63, b = (idx >> 6) & 3, br = idx >> 8;
    const float* mr = &g_mean[(br * BSZ + b) * DM];
    const float* w  = Wop + br * DM * EMB + e;
    float acc = bop[br * EMB + e];
#pragma unroll 8
    for (int k = 0; k < DM; k++) acc += mr[k] * w[k * EMB];
    g_zt[idx] = acc;
    out[br * (BSZ * EMB) + b * EMB + e] = acc;
}

// ---------------- Lorentz finale: z_h, combined_tangent, combined_h ----------------
__global__ void k_final(const float* __restrict__ esp, float* __restrict__ out)
{
    float es = tanhf(esp[0]);
    int w = threadIdx.x >> 5, lane = threadIdx.x & 31;
    __shared__ float us[NB][BSZ][EMB];

    {   // stage 1: per (branch, batch) -> z_h and logmap0
        int br = w >> 2, b = w & 3;
        float v0 = g_zt[(br * BSZ + b) * EMB + 2 * lane + 0] * es;
        float v1 = g_zt[(br * BSZ + b) * EMB + 2 * lane + 1] * es;
        float n2 = v0 * v0 + v1 * v1;
#pragma unroll
        for (int o = 16; o > 0; o >>= 1) n2 += __shfl_xor_sync(0xffffffffu, n2, o);
        float n  = sqrtf(n2);
        float nc = fminf(fmaxf(n, EPSV), MAXN);
        float sc = nc / fmaxf(n, EPSV);
        float f  = sinhf(nc) / nc;
        float sp0 = f * v0 * sc, sp1 = f * v1 * sc;
        float s2 = sp0 * sp0 + sp1 * sp1;
#pragma unroll
        for (int o = 16; o > 0; o >>= 1) s2 += __shfl_xor_sync(0xffffffffu, s2, o);
        float tc = sqrtf(1.f + s2);                       // projx time coord
        int zo = 1024 + br * (BSZ * (EMB + 1)) + b * (EMB + 1);
        if (lane == 0) out[zo] = tc;
        out[zo + 1 + 2 * lane] = sp0;
        out[zo + 2 + 2 * lane] = sp1;
        // logmap0
        float tt  = fmaxf(tc, 1.f + EPSV);
        float dg  = acoshf(tt);
        float spn = fmaxf(sqrtf(s2), EPSV);
        float ff  = dg / spn;
        us[br][b][2 * lane + 0] = ff * sp0;
        us[br][b][2 * lane + 1] = ff * sp1;
    }
    __syncthreads();
    if (w < BSZ) {     // stage 2: combined tangent + combined_h
        int b = w;
        float c0 = us[0][b][2 * lane] + us[1][b][2 * lane] + us[2][b][2 * lane] + us[3][b][2 * lane];
        float c1 = us[0][b][2 * lane + 1] + us[1][b][2 * lane + 1] + us[2][b][2 * lane + 1] + us[3][b][2 * lane + 1];
        out[2064 + b * EMB + 2 * lane + 0] = c0;
        out[2064 + b * EMB + 2 * lane + 1] = c1;
        float v0 = c0 * es, v1 = c1 * es;
        float n2 = v0 * v0 + v1 * v1;
#pragma unroll
        for (int o = 16; o > 0; o >>= 1) n2 += __shfl_xor_sync(0xffffffffu, n2, o);
        float n  = sqrtf(n2);
        float nc = fminf(fmaxf(n, EPSV), MAXN);
        float sc = nc / fmaxf(n, EPSV);
        float f  = sinhf(nc) / nc;
        float sp0 = f * v0 * sc, sp1 = f * v1 * sc;
        float s2 = sp0 * sp0 + sp1 * sp1;
#pragma unroll
        for (int o = 16; o > 0; o >>= 1) s2 += __shfl_xor_sync(0xffffffffu, s2, o);
        float tc = sqrtf(1.f + s2);
        int zo = 2320 + b * (EMB + 1);
        if (lane == 0) out[zo] = tc;
        out[zo + 1 + 2 * lane] = sp0;
        out[zo + 2 + 2 * lane] = sp1;
    }
}

// ---------------- launch ----------------
extern "C" void kernel_launch(void* const* d_in, const int* in_sizes, int n_in,
                              void* d_out, int out_size)
{
    const float* trend = (const float*)d_in[0];
    const float* seasc = (const float*)d_in[1];
    const float* seasf = (const float*)d_in[2];
    const float* resid = (const float*)d_in[3];
    const float* W_ip  = (const float*)d_in[4];
    const float* b_ip  = (const float*)d_in[5];
    const float* W_in  = (const float*)d_in[6];
    const float* conv_w= (const float*)d_in[7];
    const float* conv_b= (const float*)d_in[8];
    const float* W_x   = (const float*)d_in[9];
    const float* W_dt  = (const float*)d_in[10];
    const float* b_dt  = (const float*)d_in[11];
    const float* A_log = (const float*)d_in[12];
    const float* D_par = (const float*)d_in[13];
    const float* W_out = (const float*)d_in[14];
    const float* W_op  = (const float*)d_in[15];
    const float* b_op  = (const float*)d_in[16];
    const float* eff_s = (const float*)d_in[17];
    float* out = (float*)d_out;

    float *ph, *pxz, *pxc, *pdbl, *py;
    cudaGetSymbolAddress((void**)&ph,   g_h);
    cudaGetSymbolAddress((void**)&pxz,  g_xz);
    cudaGetSymbolAddress((void**)&pxc,  g_xc);
    cudaGetSymbolAddress((void**)&pdbl, g_dbl);
    cudaGetSymbolAddress((void**)&py,   g_y);

    k_inproj<<<(NB * NTOK * DM) / 256, 256>>>(trend, seasc, seasf, resid, W_ip, b_ip);

    for (int l = 0; l < NL; l++) {
        // xz = h @ W_in[br,l]   (4096 x 512, K=128)
        k_sgemm<<<dim3((2 * DI) / 64, NTOK / 128, NB), 256>>>(
            ph, W_in + (size_t)l * DM * 2 * DI, pxz,
            NTOK, 2 * DI, DM, NTOK * DM, NL * DM * 2 * DI, NTOK * 2 * DI);

        k_convsilu<<<(NB * NTOK * DI) / 256, 256>>>(conv_w, conv_b, l);

        // dbl = xc @ W_x[br,l]  (4096 x 40, K=256)
        k_sgemm<<<dim3(1, NTOK / 128, NB), 256>>>(
            pxc, W_x + (size_t)l * DI * 40, pdbl,
            NTOK, 40, DI, NTOK * DI, NL * DI * 40, NTOK * 40);

        k_dt<<<(NB * NTOK * DI) / 256, 256>>>(W_dt, b_dt, l);

        k_scan1<<<dim3(NCH, BSZ, NB), 256>>>(A_log, l);
        k_scan2<<<dim3(NCH, BSZ, NB), 256>>>(A_log, D_par, l);

        // h = y @ W_out[br,l]   (4096 x 128, K=256)
        k_sgemm<<<dim3(DM / 64, NTOK / 128, NB), 256>>>(
            py, W_out + (size_t)l * DI * DM, ph,
            NTOK, DM, DI, NTOK * DI, NL * DI * DM, NTOK * DM);
    }

    k_mean<<<NB * BSZ, DM>>>();
    k_head<<<(NB * BSZ * EMB) / 256, 256>>>(W_op, b_op, out);
    k_final<<<1, 512>>>(eff_s, out);
}

// round 8
// speedup vs baseline: 1.0003x; 1.0003x over previous
#include <cuda_runtime.h>
#include <math.h>

// ---------------- problem constants ----------------
#define NB   4      // branches
#define NL   3      // layers
#define BSZ  4      // batch
#define TSZ  1024   // sequence
#define DIN  32
#define DM   128    // d_model
#define DI   256    // d_inner
#define DS   16     // d_state
#define DC   4      // d_conv
#define DTR  8      // dt_rank
#define EMB  64
#define NTOK (BSZ*TSZ)      // 4096 tokens per branch
#define NCH  8              // scan chunks
#define CLEN (TSZ/NCH)      // 128 steps per chunk
#define EPSV 1e-7f
#define MAXN 10.0f

// ---------------- device scratch (no allocations allowed) ----------------
__device__ float g_h  [NB*NTOK*DM];        // 8 MB   hidden (d_model)
__device__ float g_xz [NB*NTOK*2*DI];      // 32 MB  in_proj output (xp | z)
__device__ float g_xc [NB*NTOK*DI];        // 16 MB  conv+silu output
__device__ float g_dbl[NB*NTOK*40];        // 2.6 MB dt_rank + B + C
__device__ float g_dt [NB*NTOK*DI];        // 16 MB  softplus(dt)
__device__ float g_y  [NB*NTOK*DI];        // 16 MB  scan output * silu(z)
__device__ float g_q  [NB*BSZ*NCH*DI*DS];  // 8 MB   per-chunk end state (from 0)
__device__ float g_S  [NB*BSZ*NCH*DI];     // 0.5 MB per-chunk sum(dt)
__device__ float g_mean[NB*BSZ*DM];
__device__ float g_zt [NB*BSZ*EMB];

__device__ __forceinline__ float siluf(float x) { return x / (1.f + __expf(-x)); }

// ---------------- input projection: h = x @ W_ip + b_ip ----------------
__global__ void k_inproj(const float* __restrict__ x0, const float* __restrict__ x1,
                         const float* __restrict__ x2, const float* __restrict__ x3,
                         const float* __restrict__ Wip, const float* __restrict__ bip)
{
    int idx = blockIdx.x * 256 + threadIdx.x;          // NB*NTOK*DM = 2^21
    int dm  = idx & (DM - 1);
    int n   = (idx >> 7) & (NTOK - 1);
    int br  = idx >> 19;
    const float* X = (br == 0) ? x0 : (br == 1) ? x1 : (br == 2) ? x2 : x3;
    const float* xr = X + n * DIN;
    const float* w  = Wip + br * DIN * DM + dm;
    float acc = bip[br * DM + dm];
#pragma unroll
    for (int k = 0; k < DIN; k++) acc += xr[k] * w[k * DM];
    g_h[idx] = acc;
}

// ---------------- generic batched SGEMM: C = A @ B (per branch) ----------------
// BM=128, BN=64, BK=16, 256 threads, 8x4 per thread.
__global__ __launch_bounds__(256) void k_sgemm(
    const float* __restrict__ A, const float* __restrict__ B, float* __restrict__ C,
    int M, int N, int K, int sA, int sB, int sC)
{
    const int BM = 128, BN = 64, BK = 16, TM = 8, TN = 4;
    A += (size_t)blockIdx.z * sA;
    B += (size_t)blockIdx.z * sB;
    C += (size_t)blockIdx.z * sC;
    int bm = blockIdx.y * BM, bn = blockIdx.x * BN;

    __shared__ float As[BM][BK];
    __shared__ __align__(16) float Bs[BK][BN];

    int tid  = threadIdx.x;
    int trow = (tid >> 4) * TM;
    int tcol = (tid & 15) * TN;

    float acc[TM][TN];
#pragma unroll
    for (int i = 0; i < TM; i++)
#pragma unroll
        for (int j = 0; j < TN; j++) acc[i][j] = 0.f;

    for (int k0 = 0; k0 < K; k0 += BK) {
#pragma unroll
        for (int i = 0; i < (BM * BK) / 256; i++) {      // 8 loads
            int e  = tid + i * 256;
            int m  = e >> 4, kk = e & 15;
            As[m][kk] = A[(size_t)(bm + m) * K + k0 + kk];
        }
#pragma unroll
        for (int i = 0; i < (BK * BN) / 256; i++) {      // 4 loads
            int e  = tid + i * 256;
            int kk = e >> 6, nn = e & 63;
            float v = 0.f;
            if (bn + nn < N) v = B[(size_t)(k0 + kk) * N + bn + nn];
            Bs[kk][nn] = v;
        }
        __syncthreads();
#pragma unroll
        for (int kk = 0; kk < BK; kk++) {
            float a[TM];
#pragma unroll
            for (int i = 0; i < TM; i++) a[i] = As[trow + i][kk];
            float4 bv = *reinterpret_cast<const float4*>(&Bs[kk][tcol]);
            float bb[TN] = { bv.x, bv.y, bv.z, bv.w };
#pragma unroll
            for (int i = 0; i < TM; i++)
#pragma unroll
                for (int j = 0; j < TN; j++) acc[i][j] += a[i] * bb[j];
        }
        __syncthreads();
    }
#pragma unroll
    for (int i = 0; i < TM; i++) {
        int m = bm + trow + i;
#pragma unroll
        for (int j = 0; j < TN; j++) {
            int n = bn + tcol + j;
            if (n < N) C[(size_t)m * N + n] = acc[i][j];
        }
    }
}

// ---------------- causal depthwise conv (k=4) + silu ----------------
__global__ void k_convsilu(const float* __restrict__ cw, const float* __restrict__ cb, int l)
{
    int idx = blockIdx.x * 256 + threadIdx.x;          // NB*NTOK*DI = 2^22
    int d   = idx & (DI - 1);
    int n   = (idx >> 8) & (NTOK - 1);
    int br  = idx >> 20;
    int t = n & (TSZ - 1), b = n >> 10;
    const float* w = cw + ((br * NL + l) * DI + d) * DC;
    float acc = cb[(br * NL + l) * DI + d];
    int base = (br * NTOK + b * TSZ) * (2 * DI);
#pragma unroll
    for (int k = 0; k < DC; k++) {
        int tt = t + k - (DC - 1);
        if (tt >= 0) acc += g_xz[base + tt * (2 * DI) + d] * w[k];
    }
    g_xc[idx] = siluf(acc);
}

// ---------------- dt = softplus(dbl[:,:8] @ W_dt + b_dt) ----------------
__global__ void k_dt(const float* __restrict__ Wdt, const float* __restrict__ bdt, int l)
{
    int idx = blockIdx.x * 256 + threadIdx.x;
    int d   = idx & (DI - 1);
    int n   = (idx >> 8) & (NTOK - 1);
    int br  = idx >> 20;
    const float* db = &g_dbl[(br * NTOK + n) * 40];
    const float* w  = Wdt + (br * NL + l) * DTR * DI + d;
    float acc = bdt[(br * NL + l) * DI + d];
#pragma unroll
    for (int r = 0; r < DTR; r++) acc += db[r] * w[r * DI];
    g_dt[idx] = (acc > 20.f) ? acc : log1pf(__expf(acc));
}

// ---------------- scan pass 1: per-chunk (q, S) from zero initial state ----------------
__global__ __launch_bounds__(256) void k_scan1(const float* __restrict__ Alog, int l)
{
    int c = blockIdx.x, b = blockIdx.y, br = blockIdx.z;
    int d = threadIdx.x;
    const float* ap = Alog + ((size_t)(br * NL + l) * DI + d) * DS;
    float As[DS], h[DS];
#pragma unroll
    for (int s = 0; s < DS; s++) { As[s] = -__expf(ap[s]); h[s] = 0.f; }
    float Ssum = 0.f;
    __shared__ float sB[32][DS];
    int nbase = br * NTOK + b * TSZ + c * CLEN;
    for (int tb = 0; tb < CLEN; tb += 32) {
        __syncthreads();
#pragma unroll
        for (int i = 0; i < 2; i++) {
            int e = threadIdx.x + i * 256;
            int row = e >> 4, s = e & 15;
            sB[row][s] = g_dbl[(size_t)(nbase + tb + row) * 40 + 8 + s];
        }
        __syncthreads();
#pragma unroll 4
        for (int i = 0; i < 32; i++) {
            int tok = nbase + tb + i;
            float dt = g_dt[(size_t)tok * DI + d];
            float xc = g_xc[(size_t)tok * DI + d];
            float u  = dt * xc;
            Ssum += dt;
#pragma unroll
            for (int s = 0; s < DS; s++)
                h[s] = __expf(dt * As[s]) * h[s] + u * sB[i][s];
        }
    }
    int qo = (((br * BSZ + b) * NCH + c) * DI + d) * DS;
#pragma unroll
    for (int s = 0; s < DS; s++) g_q[qo + s] = h[s];
    g_S[((br * BSZ + b) * NCH + c) * DI + d] = Ssum;
}

// ---------------- scan pass 2: fold prefix chunks, emit y*silu(z)+D*xc ----------------
__global__ __launch_bounds__(256) void k_scan2(const float* __restrict__ Alog,
                                               const float* __restrict__ Dpar, int l)
{
    int c = blockIdx.x, b = blockIdx.y, br = blockIdx.z;
    int d = threadIdx.x;
    const float* ap = Alog + ((size_t)(br * NL + l) * DI + d) * DS;
    float As[DS], h[DS];
#pragma unroll
    for (int s = 0; s < DS; s++) { As[s] = -__expf(ap[s]); h[s] = 0.f; }

    // initial state for this chunk: fold chunks 0..c-1
    for (int j = 0; j < c; j++) {
        float Sj = g_S[((br * BSZ + b) * NCH + j) * DI + d];
        int qo = (((br * BSZ + b) * NCH + j) * DI + d) * DS;
#pragma unroll
        for (int s = 0; s < DS; s++)
            h[s] = __expf(As[s] * Sj) * h[s] + g_q[qo + s];
    }
    float Dp = Dpar[(br * NL + l) * DI + d];

    __shared__ float sB[32][DS];
    __shared__ float sC[32][DS];
    int nbase = br * NTOK + b * TSZ + c * CLEN;
    for (int tb = 0; tb < CLEN; tb += 32) {
        __syncthreads();
#pragma unroll
        for (int i = 0; i < 4; i++) {
            int e = threadIdx.x + i * 256;      // 32 rows x 32 (B|C)
            int row = e >> 5, s = e & 31;
            float v = g_dbl[(size_t)(nbase + tb + row) * 40 + 8 + s];
            if (s < 16) sB[row][s] = v; else sC[row][s - 16] = v;
        }
        __syncthreads();
#pragma unroll 2
        for (int i = 0; i < 32; i++) {
            int tok = nbase + tb + i;
            float dt = g_dt[(size_t)tok * DI + d];
            float xc = g_xc[(size_t)tok * DI + d];
            float u  = dt * xc;
            float y  = 0.f;
#pragma unroll
            for (int s = 0; s < DS; s++) {
                h[s] = __expf(dt * As[s]) * h[s] + u * sB[i][s];
                y += h[s] * sC[i][s];
            }
            float z = g_xz[(size_t)tok * (2 * DI) + DI + d];
            g_y[(size_t)tok * DI + d] = (y + Dp * xc) * siluf(z);
        }
    }
}

// ---------------- mean over T ----------------
__global__ void k_mean()
{
    int g = blockIdx.x;                 // NB*BSZ = 16
    int d = threadIdx.x;                // 128
    int br = g >> 2, b = g & 3;
    int base = (br * NTOK + b * TSZ) * DM + d;
    float a0 = 0.f, a1 = 0.f, a2 = 0.f, a3 = 0.f;
    for (int t = 0; t < TSZ; t += 4) {
        a0 += g_h[base + (t + 0) * DM];
        a1 += g_h[base + (t + 1) * DM];
        a2 += g_h[base + (t + 2) * DM];
        a3 += g_h[base + (t + 3) * DM];
    }
    g_mean[g * DM + d] = (a0 + a1 + a2 + a3) * (1.f / TSZ);
}

// ---------------- head: z_t = mean @ W_op + b_op (also writes d_out) ----------------
__global__ void k_head(const float* __restrict__ Wop, const float* __restrict__ bop,
                       float* __restrict__ out)
{
    int idx = blockIdx.x * 256 + threadIdx.x;   // 1024
    int e = idx & 63, b = (idx >> 6) & 3, br = idx >> 8;
    const float* mr = &g_mean[(br * BSZ + b) * DM];
    const float* w  = Wop + br * DM * EMB + e;
    float acc = bop[br * EMB + e];
#pragma unroll 8
    for (int k = 0; k < DM; k++) acc += mr[k] * w[k * EMB];
    g_zt[idx] = acc;
    out[br * (BSZ * EMB) + b * EMB + e] = acc;
}

// ---------------- Lorentz finale: z_h, combined_tangent, combined_h ----------------
__global__ void k_final(const float* __restrict__ esp, float* __restrict__ out)
{
    float es = tanhf(esp[0]);
    int w = threadIdx.x >> 5, lane = threadIdx.x & 31;
    __shared__ float us[NB][BSZ][EMB];

    {   // stage 1: per (branch, batch) -> z_h and logmap0
        int br = w >> 2, b = w & 3;
        float v0 = g_zt[(br * BSZ + b) * EMB + 2 * lane + 0] * es;
        float v1 = g_zt[(br * BSZ + b) * EMB + 2 * lane + 1] * es;
        float n2 = v0 * v0 + v1 * v1;
#pragma unroll
        for (int o = 16; o > 0; o >>= 1) n2 += __shfl_xor_sync(0xffffffffu, n2, o);
        float n  = sqrtf(n2);
        float nc = fminf(fmaxf(n, EPSV), MAXN);
        float sc = nc / fmaxf(n, EPSV);
        float f  = sinhf(nc) / nc;
        float sp0 = f * v0 * sc, sp1 = f * v1 * sc;
        float s2 = sp0 * sp0 + sp1 * sp1;
#pragma unroll
        for (int o = 16; o > 0; o >>= 1) s2 += __shfl_xor_sync(0xffffffffu, s2, o);
        float tc = sqrtf(1.f + s2);                       // projx time coord
        int zo = 1024 + br * (BSZ * (EMB + 1)) + b * (EMB + 1);
        if (lane == 0) out[zo] = tc;
        out[zo + 1 + 2 * lane] = sp0;
        out[zo + 2 + 2 * lane] = sp1;
        // logmap0
        float tt  = fmaxf(tc, 1.f + EPSV);
        float dg  = acoshf(tt);
        float spn = fmaxf(sqrtf(s2), EPSV);
        float ff  = dg / spn;
        us[br][b][2 * lane + 0] = ff * sp0;
        us[br][b][2 * lane + 1] = ff * sp1;
    }
    __syncthreads();
    if (w < BSZ) {     // stage 2: combined tangent + combined_h
        int b = w;
        float c0 = us[0][b][2 * lane] + us[1][b][2 * lane] + us[2][b][2 * lane] + us[3][b][2 * lane];
        float c1 = us[0][b][2 * lane + 1] + us[1][b][2 * lane + 1] + us[2][b][2 * lane + 1] + us[3][b][2 * lane + 1];
        out[2064 + b * EMB + 2 * lane + 0] = c0;
        out[2064 + b * EMB + 2 * lane + 1] = c1;
        float v0 = c0 * es, v1 = c1 * es;
        float n2 = v0 * v0 + v1 * v1;
#pragma unroll
        for (int o = 16; o > 0; o >>= 1) n2 += __shfl_xor_sync(0xffffffffu, n2, o);
        float n  = sqrtf(n2);
        float nc = fminf(fmaxf(n, EPSV), MAXN);
        float sc = nc / fmaxf(n, EPSV);
        float f  = sinhf(nc) / nc;
        float sp0 = f * v0 * sc, sp1 = f * v1 * sc;
        float s2 = sp0 * sp0 + sp1 * sp1;
#pragma unroll
        for (int o = 16; o > 0; o >>= 1) s2 += __shfl_xor_sync(0xffffffffu, s2, o);
        float tc = sqrtf(1.f + s2);
        int zo = 2320 + b * (EMB + 1);
        if (lane == 0) out[zo] = tc;
        out[zo + 1 + 2 * lane] = sp0;
        out[zo + 2 + 2 * lane] = sp1;
    }
}

// ---------------- launch ----------------
extern "C" void kernel_launch(void* const* d_in, const int* in_sizes, int n_in,
                              void* d_out, int out_size)
{
    const float* trend = (const float*)d_in[0];
    const float* seasc = (const float*)d_in[1];
    const float* seasf = (const float*)d_in[2];
    const float* resid = (const float*)d_in[3];
    const float* W_ip  = (const float*)d_in[4];
    const float* b_ip  = (const float*)d_in[5];
    const float* W_in  = (const float*)d_in[6];
    const float* conv_w= (const float*)d_in[7];
    const float* conv_b= (const float*)d_in[8];
    const float* W_x   = (const float*)d_in[9];
    const float* W_dt  = (const float*)d_in[10];
    const float* b_dt  = (const float*)d_in[11];
    const float* A_log = (const float*)d_in[12];
    const float* D_par = (const float*)d_in[13];
    const float* W_out = (const float*)d_in[14];
    const float* W_op  = (const float*)d_in[15];
    const float* b_op  = (const float*)d_in[16];
    const float* eff_s = (const float*)d_in[17];
    float* out = (float*)d_out;

    float *ph, *pxz, *pxc, *pdbl, *py;
    cudaGetSymbolAddress((void**)&ph,   g_h);
    cudaGetSymbolAddress((void**)&pxz,  g_xz);
    cudaGetSymbolAddress((void**)&pxc,  g_xc);
    cudaGetSymbolAddress((void**)&pdbl, g_dbl);
    cudaGetSymbolAddress((void**)&py,   g_y);

    k_inproj<<<(NB * NTOK * DM) / 256, 256>>>(trend, seasc, seasf, resid, W_ip, b_ip);

    for (int l = 0; l < NL; l++) {
        // xz = h @ W_in[br,l]   (4096 x 512, K=128)
        k_sgemm<<<dim3((2 * DI) / 64, NTOK / 128, NB), 256>>>(
            ph, W_in + (size_t)l * DM * 2 * DI, pxz,
            NTOK, 2 * DI, DM, NTOK * DM, NL * DM * 2 * DI, NTOK * 2 * DI);

        k_convsilu<<<(NB * NTOK * DI) / 256, 256>>>(conv_w, conv_b, l);

        // dbl = xc @ W_x[br,l]  (4096 x 40, K=256)
        k_sgemm<<<dim3(1, NTOK / 128, NB), 256>>>(
            pxc, W_x + (size_t)l * DI * 40, pdbl,
            NTOK, 40, DI, NTOK * DI, NL * DI * 40, NTOK * 40);

        k_dt<<<(NB * NTOK * DI) / 256, 256>>>(W_dt, b_dt, l);

        k_scan1<<<dim3(NCH, BSZ, NB), 256>>>(A_log, l);
        k_scan2<<<dim3(NCH, BSZ, NB), 256>>>(A_log, D_par, l);

        // h = y @ W_out[br,l]   (4096 x 128, K=256)
        k_sgemm<<<dim3(DM / 64, NTOK / 128, NB), 256>>>(
            py, W_out + (size_t)l * DI * DM, ph,
            NTOK, DM, DI, NTOK * DI, NL * DI * DM, NTOK * DM);
    }

    k_mean<<<NB * BSZ, DM>>>();
    k_head<<<(NB * BSZ * EMB) / 256, 256>>>(W_op, b_op, out);
    k_final<<<1, 512>>>(eff_s, out);
}

// round 9
// speedup vs baseline: 1.0056x; 1.0053x over previous
#include <cuda_runtime.h>
#include <math.h>

// ---------------- problem constants ----------------
#define NB   4      // branches
#define NL   3      // layers
#define BSZ  4      // batch
#define TSZ  1024   // sequence
#define DIN  32
#define DM   128    // d_model
#define DI   256    // d_inner
#define DS   16     // d_state
#define DC   4      // d_conv
#define DTR  8      // dt_rank
#define EMB  64
#define NTOK (BSZ*TSZ)      // 4096 tokens per branch
#define NCH  8              // scan chunks
#define CLEN (TSZ/NCH)      // 128 steps per chunk
#define EPSV 1e-7f
#define MAXN 10.0f

// ---------------- device scratch (no allocations allowed) ----------------
__device__ float g_h  [NB*NTOK*DM];        // 8 MB   hidden (d_model)
__device__ float g_xz [NB*NTOK*2*DI];      // 32 MB  in_proj output (xp | z)
__device__ float g_xc [NB*NTOK*DI];        // 16 MB  conv+silu output
__device__ float g_dbl[NB*NTOK*40];        // 2.6 MB dt_rank + B + C
__device__ float g_dt [NB*NTOK*DI];        // 16 MB  softplus(dt)
__device__ float g_y  [NB*NTOK*DI];        // 16 MB  scan output * silu(z)
__device__ float g_q  [NB*BSZ*NCH*DI*DS];  // 8 MB   per-chunk end state (from 0)
__device__ float g_S  [NB*BSZ*NCH*DI];     // 0.5 MB per-chunk sum(dt)
__device__ float g_mean[NB*BSZ*DM];
__device__ float g_zt [NB*BSZ*EMB];

__device__ __forceinline__ float siluf(float x) { return x / (1.f + __expf(-x)); }

// ---------------- input projection: h = x @ W_ip + b_ip ----------------
__global__ void k_inproj(const float* __restrict__ x0, const float* __restrict__ x1,
                         const float* __restrict__ x2, const float* __restrict__ x3,
                         const float* __restrict__ Wip, const float* __restrict__ bip)
{
    int idx = blockIdx.x * 256 + threadIdx.x;          // NB*NTOK*DM = 2^21
    int dm  = idx & (DM - 1);
    int n   = (idx >> 7) & (NTOK - 1);
    int br  = idx >> 19;
    const float* X = (br == 0) ? x0 : (br == 1) ? x1 : (br == 2) ? x2 : x3;
    const float* xr = X + n * DIN;
    const float* w  = Wip + br * DIN * DM + dm;
    float acc = bip[br * DM + dm];
#pragma unroll
    for (int k = 0; k < DIN; k++) acc += xr[k] * w[k * DM];
    g_h[idx] = acc;
}

// ---------------- generic batched SGEMM: C = A @ B (per branch) ----------------
// BM=128, BN=64, BK=16, 256 threads, 8x4 per thread.
__global__ __launch_bounds__(256) void k_sgemm(
    const float* __restrict__ A, const float* __restrict__ B, float* __restrict__ C,
    int M, int N, int K, int sA, int sB, int sC)
{
    const int BM = 128, BN = 64, BK = 16, TM = 8, TN = 4;
    A += (size_t)blockIdx.z * sA;
    B += (size_t)blockIdx.z * sB;
    C += (size_t)blockIdx.z * sC;
    int bm = blockIdx.y * BM, bn = blockIdx.x * BN;

    __shared__ float As[BM][BK];
    __shared__ __align__(16) float Bs[BK][BN];

    int tid  = threadIdx.x;
    int trow = (tid >> 4) * TM;
    int tcol = (tid & 15) * TN;

    float acc[TM][TN];
#pragma unroll
    for (int i = 0; i < TM; i++)
#pragma unroll
        for (int j = 0; j < TN; j++) acc[i][j] = 0.f;

    for (int k0 = 0; k0 < K; k0 += BK) {
#pragma unroll
        for (int i = 0; i < (BM * BK) / 256; i++) {      // 8 loads
            int e  = tid + i * 256;
            int m  = e >> 4, kk = e & 15;
            As[m][kk] = A[(size_t)(bm + m) * K + k0 + kk];
        }
#pragma unroll
        for (int i = 0; i < (BK * BN) / 256; i++) {      // 4 loads
            int e  = tid + i * 256;
            int kk = e >> 6, nn = e & 63;
            float v = 0.f;
            if (bn + nn < N) v = B[(size_t)(k0 + kk) * N + bn + nn];
            Bs[kk][nn] = v;
        }
        __syncthreads();
#pragma unroll
        for (int kk = 0; kk < BK; kk++) {
            float a[TM];
#pragma unroll
            for (int i = 0; i < TM; i++) a[i] = As[trow + i][kk];
            float4 bv = *reinterpret_cast<const float4*>(&Bs[kk][tcol]);
            float bb[TN] = { bv.x, bv.y, bv.z, bv.w };
#pragma unroll
            for (int i = 0; i < TM; i++)
#pragma unroll
                for (int j = 0; j < TN; j++) acc[i][j] += a[i] * bb[j];
        }
        __syncthreads();
    }
#pragma unroll
    for (int i = 0; i < TM; i++) {
        int m = bm + trow + i;
#pragma unroll
        for (int j = 0; j < TN; j++) {
            int n = bn + tcol + j;
            if (n < N) C[(size_t)m * N + n] = acc[i][j];
        }
    }
}

// ---------------- causal depthwise conv (k=4) + silu ----------------
__global__ void k_convsilu(const float* __restrict__ cw, const float* __restrict__ cb, int l)
{
    int idx = blockIdx.x * 256 + threadIdx.x;          // NB*NTOK*DI = 2^22
    int d   = idx & (DI - 1);
    int n   = (idx >> 8) & (NTOK - 1);
    int br  = idx >> 20;
    int t = n & (TSZ - 1), b = n >> 10;
    const float* w = cw + ((br * NL + l) * DI + d) * DC;
    float acc = cb[(br * NL + l) * DI + d];
    int base = (br * NTOK + b * TSZ) * (2 * DI);
#pragma unroll
    for (int k = 0; k < DC; k++) {
        int tt = t + k - (DC - 1);
        if (tt >= 0) acc += g_xz[base + tt * (2 * DI) + d] * w[k];
    }
    g_xc[idx] = siluf(acc);
}

// ---------------- dt = softplus(dbl[:,:8] @ W_dt + b_dt) ----------------
__global__ void k_dt(const float* __restrict__ Wdt, const float* __restrict__ bdt, int l)
{
    int idx = blockIdx.x * 256 + threadIdx.x;
    int d   = idx & (DI - 1);
    int n   = (idx >> 8) & (NTOK - 1);
    int br  = idx >> 20;
    const float* db = &g_dbl[(br * NTOK + n) * 40];
    const float* w  = Wdt + (br * NL + l) * DTR * DI + d;
    float acc = bdt[(br * NL + l) * DI + d];
#pragma unroll
    for (int r = 0; r < DTR; r++) acc += db[r] * w[r * DI];
    g_dt[idx] = (acc > 20.f) ? acc : log1pf(__expf(acc));
}

// ---------------- scan pass 1: per-chunk (q, S) from zero initial state ----------------
__global__ __launch_bounds__(256) void k_scan1(const float* __restrict__ Alog, int l)
{
    int c = blockIdx.x, b = blockIdx.y, br = blockIdx.z;
    int d = threadIdx.x;
    const float* ap = Alog + ((size_t)(br * NL + l) * DI + d) * DS;
    float As[DS], h[DS];
#pragma unroll
    for (int s = 0; s < DS; s++) { As[s] = -__expf(ap[s]); h[s] = 0.f; }
    float Ssum = 0.f;
    __shared__ float sB[32][DS];
    int nbase = br * NTOK + b * TSZ + c * CLEN;
    for (int tb = 0; tb < CLEN; tb += 32) {
        __syncthreads();
#pragma unroll
        for (int i = 0; i < 2; i++) {
            int e = threadIdx.x + i * 256;
            int row = e >> 4, s = e & 15;
            sB[row][s] = g_dbl[(size_t)(nbase + tb + row) * 40 + 8 + s];
        }
        __syncthreads();
#pragma unroll 4
        for (int i = 0; i < 32; i++) {
            int tok = nbase + tb + i;
            float dt = g_dt[(size_t)tok * DI + d];
            float xc = g_xc[(size_t)tok * DI + d];
            float u  = dt * xc;
            Ssum += dt;
#pragma unroll
            for (int s = 0; s < DS; s++)
                h[s] = __expf(dt * As[s]) * h[s] + u * sB[i][s];
        }
    }
    int qo = (((br * BSZ + b) * NCH + c) * DI + d) * DS;
#pragma unroll
    for (int s = 0; s < DS; s++) g_q[qo + s] = h[s];
    g_S[((br * BSZ + b) * NCH + c) * DI + d] = Ssum;
}

// ---------------- scan pass 2: fold prefix chunks, emit y*silu(z)+D*xc ----------------
__global__ __launch_bounds__(256) void k_scan2(const float* __restrict__ Alog,
                                               const float* __restrict__ Dpar, int l)
{
    int c = blockIdx.x, b = blockIdx.y, br = blockIdx.z;
    int d = threadIdx.x;
    const float* ap = Alog + ((size_t)(br * NL + l) * DI + d) * DS;
    float As[DS], h[DS];
#pragma unroll
    for (int s = 0; s < DS; s++) { As[s] = -__expf(ap[s]); h[s] = 0.f; }

    // initial state for this chunk: fold chunks 0..c-1
    for (int j = 0; j < c; j++) {
        float Sj = g_S[((br * BSZ + b) * NCH + j) * DI + d];
        int qo = (((br * BSZ + b) * NCH + j) * DI + d) * DS;
#pragma unroll
        for (int s = 0; s < DS; s++)
            h[s] = __expf(As[s] * Sj) * h[s] + g_q[qo + s];
    }
    float Dp = Dpar[(br * NL + l) * DI + d];

    __shared__ float sB[32][DS];
    __shared__ float sC[32][DS];
    int nbase = br * NTOK + b * TSZ + c * CLEN;
    for (int tb = 0; tb < CLEN; tb += 32) {
        __syncthreads();
#pragma unroll
        for (int i = 0; i < 4; i++) {
            int e = threadIdx.x + i * 256;      // 32 rows x 32 (B|C)
            int row = e >> 5, s = e & 31;
            float v = g_dbl[(size_t)(nbase + tb + row) * 40 + 8 + s];
            if (s < 16) sB[row][s] = v; else sC[row][s - 16] = v;
        }
        __syncthreads();
#pragma unroll 2
        for (int i = 0; i < 32; i++) {
            int tok = nbase + tb + i;
            float dt = g_dt[(size_t)tok * DI + d];
            float xc = g_xc[(size_t)tok * DI + d];
            float u  = dt * xc;
            float y  = 0.f;
#pragma unroll
            for (int s = 0; s < DS; s++) {
                h[s] = __expf(dt * As[s]) * h[s] + u * sB[i][s];
                y += h[s] * sC[i][s];
            }
            float z = g_xz[(size_t)tok * (2 * DI) + DI + d];
            g_y[(size_t)tok * DI + d] = (y + Dp * xc) * siluf(z);
        }
    }
}

// ---------------- mean over T ----------------
__global__ void k_mean()
{
    int g = blockIdx.x;                 // NB*BSZ = 16
    int d = threadIdx.x;                // 128
    int br = g >> 2, b = g & 3;
    int base = (br * NTOK + b * TSZ) * DM + d;
    float a0 = 0.f, a1 = 0.f, a2 = 0.f, a3 = 0.f;
    for (int t = 0; t < TSZ; t += 4) {
        a0 += g_h[base + (t + 0) * DM];
        a1 += g_h[base + (t + 1) * DM];
        a2 += g_h[base + (t + 2) * DM];
        a3 += g_h[base + (t + 3) * DM];
    }
    g_mean[g * DM + d] = (a0 + a1 + a2 + a3) * (1.f / TSZ);
}

// ---------------- head: z_t = mean @ W_op + b_op (also writes d_out) ----------------
__global__ void k_head(const float* __restrict__ Wop, const float* __restrict__ bop,
                       float* __restrict__ out)
{
    int idx = blockIdx.x * 256 + threadIdx.x;   // 1024
    int e = idx & 63, b = (idx >> 6) & 3, br = idx >> 8;
    const float* mr = &g_mean[(br * BSZ + b) * DM];
    const float* w  = Wop + br * DM * EMB + e;
    float acc = bop[br * EMB + e];
#pragma unroll 8
    for (int k = 0; k < DM; k++) acc += mr[k] * w[k * EMB];
    g_zt[idx] = acc;
    out[br * (BSZ * EMB) + b * EMB + e] = acc;
}

// ---------------- Lorentz finale: z_h, combined_tangent, combined_h ----------------
__global__ void k_final(const float* __restrict__ esp, float* __restrict__ out)
{
    float es = tanhf(esp[0]);
    int w = threadIdx.x >> 5, lane = threadIdx.x & 31;
    __shared__ float us[NB][BSZ][EMB];

    {   // stage 1: per (branch, batch) -> z_h and logmap0
        int br = w >> 2, b = w & 3;
        float v0 = g_zt[(br * BSZ + b) * EMB + 2 * lane + 0] * es;
        float v1 = g_zt[(br * BSZ + b) * EMB + 2 * lane + 1] * es;
        float n2 = v0 * v0 + v1 * v1;
#pragma unroll
        for (int o = 16; o > 0; o >>= 1) n2 += __shfl_xor_sync(0xffffffffu, n2, o);
        float n  = sqrtf(n2);
        float nc = fminf(fmaxf(n, EPSV), MAXN);
        float sc = nc / fmaxf(n, EPSV);
        float f  = sinhf(nc) / nc;
        float sp0 = f * v0 * sc, sp1 = f * v1 * sc;
        float s2 = sp0 * sp0 + sp1 * sp1;
#pragma unroll
        for (int o = 16; o > 0; o >>= 1) s2 += __shfl_xor_sync(0xffffffffu, s2, o);
        float tc = sqrtf(1.f + s2);                       // projx time coord
        int zo = 1024 + br * (BSZ * (EMB + 1)) + b * (EMB + 1);
        if (lane == 0) out[zo] = tc;
        out[zo + 1 + 2 * lane] = sp0;
        out[zo + 2 + 2 * lane] = sp1;
        // logmap0
        float tt  = fmaxf(tc, 1.f + EPSV);
        float dg  = acoshf(tt);
        float spn = fmaxf(sqrtf(s2), EPSV);
        float ff  = dg / spn;
        us[br][b][2 * lane + 0] = ff * sp0;
        us[br][b][2 * lane + 1] = ff * sp1;
    }
    __syncthreads();
    if (w < BSZ) {     // stage 2: combined tangent + combined_h
        int b = w;
        float c0 = us[0][b][2 * lane] + us[1][b][2 * lane] + us[2][b][2 * lane] + us[3][b][2 * lane];
        float c1 = us[0][b][2 * lane + 1] + us[1][b][2 * lane + 1] + us[2][b][2 * lane + 1] + us[3][b][2 * lane + 1];
        out[2064 + b * EMB + 2 * lane + 0] = c0;
        out[2064 + b * EMB + 2 * lane + 1] = c1;
        float v0 = c0 * es, v1 = c1 * es;
        float n2 = v0 * v0 + v1 * v1;
#pragma unroll
        for (int o = 16; o > 0; o >>= 1) n2 += __shfl_xor_sync(0xffffffffu, n2, o);
        float n  = sqrtf(n2);
        float nc = fminf(fmaxf(n, EPSV), MAXN);
        float sc = nc / fmaxf(n, EPSV);
        float f  = sinhf(nc) / nc;
        float sp0 = f * v0 * sc, sp1 = f * v1 * sc;
        float s2 = sp0 * sp0 + sp1 * sp1;
#pragma unroll
        for (int o = 16; o > 0; o >>= 1) s2 += __shfl_xor_sync(0xffffffffu, s2, o);
        float tc = sqrtf(1.f + s2);
        int zo = 2320 + b * (EMB + 1);
        if (lane == 0) out[zo] = tc;
        out[zo + 1 + 2 * lane] = sp0;
        out[zo + 2 + 2 * lane] = sp1;
    }
}

// ---------------- launch ----------------
extern "C" void kernel_launch(void* const* d_in, const int* in_sizes, int n_in,
                              void* d_out, int out_size)
{
    const float* trend = (const float*)d_in[0];
    const float* seasc = (const float*)d_in[1];
    const float* seasf = (const float*)d_in[2];
    const float* resid = (const float*)d_in[3];
    const float* W_ip  = (const float*)d_in[4];
    const float* b_ip  = (const float*)d_in[5];
    const float* W_in  = (const float*)d_in[6];
    const float* conv_w= (const float*)d_in[7];
    const float* conv_b= (const float*)d_in[8];
    const float* W_x   = (const float*)d_in[9];
    const float* W_dt  = (const float*)d_in[10];
    const float* b_dt  = (const float*)d_in[11];
    const float* A_log = (const float*)d_in[12];
    const float* D_par = (const float*)d_in[13];
    const float* W_out = (const float*)d_in[14];
    const float* W_op  = (const float*)d_in[15];
    const float* b_op  = (const float*)d_in[16];
    const float* eff_s = (const float*)d_in[17];
    float* out = (float*)d_out;

    float *ph, *pxz, *pxc, *pdbl, *py;
    cudaGetSymbolAddress((void**)&ph,   g_h);
    cudaGetSymbolAddress((void**)&pxz,  g_xz);
    cudaGetSymbolAddress((void**)&pxc,  g_xc);
    cudaGetSymbolAddress((void**)&pdbl, g_dbl);
    cudaGetSymbolAddress((void**)&py,   g_y);

    k_inproj<<<(NB * NTOK * DM) / 256, 256>>>(trend, seasc, seasf, resid, W_ip, b_ip);

    for (int l = 0; l < NL; l++) {
        // xz = h @ W_in[br,l]   (4096 x 512, K=128)
        k_sgemm<<<dim3((2 * DI) / 64, NTOK / 128, NB), 256>>>(
            ph, W_in + (size_t)l * DM * 2 * DI, pxz,
            NTOK, 2 * DI, DM, NTOK * DM, NL * DM * 2 * DI, NTOK * 2 * DI);

        k_convsilu<<<(NB * NTOK * DI) / 256, 256>>>(conv_w, conv_b, l);

        // dbl = xc @ W_x[br,l]  (4096 x 40, K=256)
        k_sgemm<<<dim3(1, NTOK / 128, NB), 256>>>(
            pxc, W_x + (size_t)l * DI * 40, pdbl,
            NTOK, 40, DI, NTOK * DI, NL * DI * 40, NTOK * 40);

        k_dt<<<(NB * NTOK * DI) / 256, 256>>>(W_dt, b_dt, l);

        k_scan1<<<dim3(NCH, BSZ, NB), 256>>>(A_log, l);
        k_scan2<<<dim3(NCH, BSZ, NB), 256>>>(A_log, D_par, l);

        // h = y @ W_out[br,l]   (4096 x 128, K=256)
        k_sgemm<<<dim3(DM / 64, NTOK / 128, NB), 256>>>(
            py, W_out + (size_t)l * DI * DM, ph,
            NTOK, DM, DI, NTOK * DI, NL * DI * DM, NTOK * DM);
    }

    k_mean<<<NB * BSZ, DM>>>();
    k_head<<<(NB * BSZ * EMB) / 256, 256>>>(W_op, b_op, out);
    k_final<<<1, 512>>>(eff_s, out);
}